// round 11
// baseline (speedup 1.0000x reference)
#include <cuda_runtime.h>
#include <cuda_fp16.h>
#include <cstdint>

#define T_DIM 1024
#define BT 128
#define BS 64
#define KSF 68           // K f32 staging stride (words)
#define VSF 72           // V f32 staging stride (words)
#define KS 72            // Kh f16x2 tile stride (words): banks 8*m4+g distinct
#define VS 36            // Vh f16x2 tile stride (words): banks 4*g+m4 distinct
#define BUF_WORDS (64 * KSF + 64 * VSF)   // 8960 floats per f32 buffer

// bit-packed mask: 8 batches x 1024 rows x 1024 bits = 1 MB
__device__ __align__(16) uint32_t g_maskbits[8u * 1024u * 32u];

__device__ __forceinline__ float ex2(float x) {
    float r; asm("ex2.approx.f32 %0, %1;" : "=f"(r) : "f"(x)); return r;
}
__device__ __forceinline__ uint32_t packh2(float lo, float hi) {
    __half2 h = __floats2half2_rn(lo, hi);   // .x = lo (low 16 bits)
    return *(uint32_t*)&h;
}
__device__ __forceinline__ void cp16(uint32_t dst, const float* src) {
    asm volatile("cp.async.cg.shared.global [%0], [%1], 16;" :: "r"(dst), "l"(src));
}

__device__ __forceinline__ void mma_f16(float d[4], const uint32_t a[4],
                                        uint32_t b0, uint32_t b1) {
    asm volatile(
        "mma.sync.aligned.m16n8k16.row.col.f32.f16.f16.f32 "
        "{%0,%1,%2,%3}, {%4,%5,%6,%7}, {%8,%9}, {%0,%1,%2,%3};\n"
        : "+f"(d[0]), "+f"(d[1]), "+f"(d[2]), "+f"(d[3])
        : "r"(a[0]), "r"(a[1]), "r"(a[2]), "r"(a[3]), "r"(b0), "r"(b1));
}

// ---------------- mask pre-pack (int32 -> bits) ----------------
__global__ void pack_mask_bits_kernel(const int* __restrict__ m) {
    uint32_t w = blockIdx.x * 256 + threadIdx.x;
    const int4* p = (const int4*)(m + (size_t)w * 32);
    uint32_t bits = 0;
    #pragma unroll
    for (int j = 0; j < 8; j++) {
        int4 v = p[j];
        bits |= (v.x != 0 ? 1u : 0u) << (4 * j + 0);
        bits |= (v.y != 0 ? 1u : 0u) << (4 * j + 1);
        bits |= (v.z != 0 ? 1u : 0u) << (4 * j + 2);
        bits |= (v.w != 0 ? 1u : 0u) << (4 * j + 3);
    }
    g_maskbits[w] = bits;
}

__global__ __launch_bounds__(128, 2) void attn_flash_kernel(
    const float* __restrict__ qkv,
    const float* __restrict__ qk_bias,
    float* __restrict__ out)
{
    extern __shared__ __align__(16) float dyns[];
    // layout: [f32 buf0 | f32 buf1 | Kh (32*KS u32) | Vh (64*VS u32)]
    uint32_t* Kh = (uint32_t*)(dyns + 2 * BUF_WORDS);
    uint32_t* Vh = Kh + 32 * KS;

    const int tile_t = blockIdx.x;   // 0..7
    const int bh = blockIdx.y;       // 0..127
    const int tid = threadIdx.x;
    const int lane = tid & 31;
    const int g = lane >> 2;
    const int m4 = lane & 3;

    const float* qp = qkv + (size_t)bh * 192 * T_DIM;
    const float* kp = qp + 64 * T_DIM;
    const float* vp = qp + 128 * T_DIM;
    const uint32_t* mb = g_maskbits + (size_t)(bh & 7) * 1024u * 32u;

    const int t0c = tile_t * BT;
    const int tb = (tid >> 5) * 32;
    const int t0 = t0c + tb;
    const float bias2 = qk_bias[0] * 1.4426950408889634f;
    const float scale2 = 0.125f * 1.4426950408889634f;

    // mask row bases (fixed across stages)
    const uint32_t* mrow0l = mb + (size_t)(t0 + g) * 32;
    const uint32_t* mrow0h = mb + (size_t)(t0 + g + 8) * 32;
    const uint32_t* mrow1l = mb + (size_t)(t0 + 16 + g) * 32;
    const uint32_t* mrow1h = mb + (size_t)(t0 + 24 + g) * 32;

    // ---- Q fragments (fp16 m16n8k16 A layout), loaded once ----
    uint32_t qf[2][4][4];
    #pragma unroll
    for (int r = 0; r < 2; r++) {
        const int t = t0 + 16 * r + g;
        #pragma unroll
        for (int k4 = 0; k4 < 4; k4++) {
            const int c0 = 16 * k4 + 2 * m4;
            qf[r][k4][0] = packh2(qp[(size_t)c0 * T_DIM + t],           qp[(size_t)(c0 + 1) * T_DIM + t]);
            qf[r][k4][1] = packh2(qp[(size_t)c0 * T_DIM + t + 8],       qp[(size_t)(c0 + 1) * T_DIM + t + 8]);
            qf[r][k4][2] = packh2(qp[(size_t)(c0 + 8) * T_DIM + t],     qp[(size_t)(c0 + 9) * T_DIM + t]);
            qf[r][k4][3] = packh2(qp[(size_t)(c0 + 8) * T_DIM + t + 8], qp[(size_t)(c0 + 9) * T_DIM + t + 8]);
        }
    }

    float o[2][8][4];
    #pragma unroll
    for (int r = 0; r < 2; r++)
        #pragma unroll
        for (int n = 0; n < 8; n++)
            { o[r][n][0]=0.f; o[r][n][1]=0.f; o[r][n][2]=0.f; o[r][n][3]=0.f; }
    float lr[2]  = {0.f, 0.f};
    float lrh[2] = {0.f, 0.f};

    const uint32_t smem_base = (uint32_t)__cvta_generic_to_shared(dyns);
    const int crow = tid >> 4;          // staging row base
    const int cj = tid & 15;            // 16B chunk in row

    // ---- prologue: stage 0 f32 loads into buffer 0 ----
    {
        const uint32_t kb = smem_base;
        const uint32_t vb = smem_base + 64 * KSF * 4;
        #pragma unroll
        for (int it = 0; it < 8; it++) {
            int c = crow + it * 8;
            cp16(kb + (uint32_t)(c * KSF + cj * 4) * 4, kp + (size_t)c * T_DIM + cj * 4);
            cp16(vb + (uint32_t)(c * VSF + cj * 4) * 4, vp + (size_t)c * T_DIM + cj * 4);
        }
        asm volatile("cp.async.commit_group;" ::: "memory");
    }

    for (int st = 0; st < 16; st++) {
        asm volatile("cp.async.wait_group 0;" ::: "memory");
        __syncthreads();   // f32 buf(st) ready; f16 tile reads of st-1 complete

        // ---- issue next stage's f32 loads into the other buffer ----
        if (st < 15) {
            const int s1 = (st + 1) * BS;
            const uint32_t base1 = smem_base + (uint32_t)(((st + 1) & 1) * BUF_WORDS) * 4;
            const uint32_t kb = base1;
            const uint32_t vb = base1 + 64 * KSF * 4;
            #pragma unroll
            for (int it = 0; it < 8; it++) {
                int c = crow + it * 8;
                cp16(kb + (uint32_t)(c * KSF + cj * 4) * 4, kp + (size_t)c * T_DIM + s1 + cj * 4);
                cp16(vb + (uint32_t)(c * VSF + cj * 4) * 4, vp + (size_t)c * T_DIM + s1 + cj * 4);
            }
            asm volatile("cp.async.commit_group;" ::: "memory");
        }

        const float* Kf = dyns + (st & 1) * BUF_WORDS;
        const float* Vf = Kf + 64 * KSF;

        // ---- conversion pass: f32 staging -> f16x2 tiles ----
        // K: Kh[c2][s] = half2(K[2c2][s], K[2c2+1][s]); 512 tasks (32 c2 x 16 chunks)
        #pragma unroll
        for (int it = 0; it < 4; it++) {
            int task = tid + it * 128;
            int c2 = task >> 4;
            int s = (task & 15) * 4;
            float4 k0 = *(const float4*)(Kf + (2 * c2) * KSF + s);
            float4 k1 = *(const float4*)(Kf + (2 * c2 + 1) * KSF + s);
            uint4 w;
            w.x = packh2(k0.x, k1.x);
            w.y = packh2(k0.y, k1.y);
            w.z = packh2(k0.z, k1.z);
            w.w = packh2(k0.w, k1.w);
            *(uint4*)&Kh[c2 * KS + s] = w;
        }
        // V: Vh[c][s2] = half2(V[c][2s2], V[c][2s2+1]); 1024 tasks (64 c x 16 chunks)
        #pragma unroll
        for (int it = 0; it < 8; it++) {
            int task = tid + it * 128;
            int c = task >> 4;
            int j = task & 15;
            float4 v4 = *(const float4*)(Vf + c * VSF + 4 * j);
            uint2 w;
            w.x = packh2(v4.x, v4.y);
            w.y = packh2(v4.z, v4.w);
            *(uint2*)&Vh[c * VS + 2 * j] = w;
        }
        __syncthreads();

        // ---- hoisted mask bit loads ----
        uint2 m0l = *(const uint2*)(mrow0l + st * 2);
        uint2 m0h = *(const uint2*)(mrow0h + st * 2);
        uint2 m1l = *(const uint2*)(mrow1l + st * 2);
        uint2 m1h = *(const uint2*)(mrow1h + st * 2);

        // ---- S = Q^T K : lean f16 fragment loads ----
        float sacc[2][8][4];
        #pragma unroll
        for (int r = 0; r < 2; r++)
            #pragma unroll
            for (int n = 0; n < 8; n++)
                { sacc[r][n][0]=0.f; sacc[r][n][1]=0.f; sacc[r][n][2]=0.f; sacc[r][n][3]=0.f; }
        #pragma unroll
        for (int k4 = 0; k4 < 4; k4++) {
            const uint32_t* kr0 = &Kh[(8 * k4 + m4) * KS];
            const uint32_t* kr1 = kr0 + 4 * KS;
            #pragma unroll
            for (int n = 0; n < 8; n++) {
                uint32_t b0 = kr0[8 * n + g];
                uint32_t b1 = kr1[8 * n + g];
                mma_f16(sacc[0][n], qf[0][k4], b0, b1);
                mma_f16(sacc[1][n], qf[1][k4], b0, b1);
            }
        }

        // ---- mask + exp2 + row sums ----
        #pragma unroll
        for (int r = 0; r < 2; r++) {
            uint2 ml = (r == 0) ? m0l : m1l;
            uint2 mh = (r == 0) ? m0h : m1h;
            uint32_t lx = ml.x >> (2 * m4), ly = ml.y >> (2 * m4);
            uint32_t hx = mh.x >> (2 * m4), hy = mh.y >> (2 * m4);
            #pragma unroll
            for (int n = 0; n < 8; n++) {
                uint32_t wl = ((n < 4) ? lx : ly) >> (8 * (n & 3));
                uint32_t wh = ((n < 4) ? hx : hy) >> (8 * (n & 3));
                float e00 = ex2(fmaf(sacc[r][n][0], scale2, bias2));
                float e01 = ex2(fmaf(sacc[r][n][1], scale2, bias2));
                float e10 = ex2(fmaf(sacc[r][n][2], scale2, bias2));
                float e11 = ex2(fmaf(sacc[r][n][3], scale2, bias2));
                float p00 = (wl & 1u) ? e00 : 0.f;
                float p01 = (wl & 2u) ? e01 : 0.f;
                float p10 = (wh & 1u) ? e10 : 0.f;
                float p11 = (wh & 2u) ? e11 : 0.f;
                sacc[r][n][0] = p00; sacc[r][n][1] = p01;
                sacc[r][n][2] = p10; sacc[r][n][3] = p11;
                lr[r]  += p00 + p01;
                lrh[r] += p10 + p11;
            }
        }

        // ---- O += P V^T (A-frag = packed S C-frag pairs) ----
        #pragma unroll
        for (int k4 = 0; k4 < 4; k4++) {
            uint32_t a0[4], a1[4];
            a0[0] = packh2(sacc[0][2 * k4][0],     sacc[0][2 * k4][1]);
            a0[1] = packh2(sacc[0][2 * k4][2],     sacc[0][2 * k4][3]);
            a0[2] = packh2(sacc[0][2 * k4 + 1][0], sacc[0][2 * k4 + 1][1]);
            a0[3] = packh2(sacc[0][2 * k4 + 1][2], sacc[0][2 * k4 + 1][3]);
            a1[0] = packh2(sacc[1][2 * k4][0],     sacc[1][2 * k4][1]);
            a1[1] = packh2(sacc[1][2 * k4][2],     sacc[1][2 * k4][3]);
            a1[2] = packh2(sacc[1][2 * k4 + 1][0], sacc[1][2 * k4 + 1][1]);
            a1[3] = packh2(sacc[1][2 * k4 + 1][2], sacc[1][2 * k4 + 1][3]);
            #pragma unroll
            for (int n = 0; n < 8; n++) {
                const uint32_t* vr = &Vh[(8 * n + g) * VS + 8 * k4 + m4];
                uint32_t b0 = vr[0];
                uint32_t b1 = vr[4];
                mma_f16(o[0][n], a0, b0, b1);
                mma_f16(o[1][n], a1, b0, b1);
            }
        }
    }

    // ---- deferred row-sum reduction ----
    #pragma unroll
    for (int r = 0; r < 2; r++) {
        lr[r]  += __shfl_xor_sync(0xffffffffu, lr[r], 1);
        lr[r]  += __shfl_xor_sync(0xffffffffu, lr[r], 2);
        lrh[r] += __shfl_xor_sync(0xffffffffu, lrh[r], 1);
        lrh[r] += __shfl_xor_sync(0xffffffffu, lrh[r], 2);
    }

    float* ob = out + (size_t)bh * 64 * T_DIM;
    #pragma unroll
    for (int r = 0; r < 2; r++) {
        float il0 = 1.f / lr[r];
        float il1 = 1.f / lrh[r];
        #pragma unroll
        for (int n = 0; n < 8; n++) {
            int c = 8 * n + 2 * m4;
            int t = t0 + 16 * r + g;
            ob[(size_t)c       * T_DIM + t]     = o[r][n][0] * il0;
            ob[(size_t)(c + 1) * T_DIM + t]     = o[r][n][1] * il0;
            ob[(size_t)c       * T_DIM + t + 8] = o[r][n][2] * il1;
            ob[(size_t)(c + 1) * T_DIM + t + 8] = o[r][n][3] * il1;
        }
    }
}

extern "C" void kernel_launch(void* const* d_in, const int* in_sizes, int n_in,
                              void* d_out, int out_size) {
    const float* qkv = (const float*)d_in[0];
    const int* mask = (const int*)d_in[1];
    const float* bias = (const float*)d_in[2];
    float* out = (float*)d_out;

    pack_mask_bits_kernel<<<1024, 256>>>(mask);

    const int dyn_smem = 2 * BUF_WORDS * 4 + 32 * KS * 4 + 64 * VS * 4;  // 90112 B
    static int attr_set = 0;
    if (!attr_set) {
        cudaFuncSetAttribute(attn_flash_kernel,
                             cudaFuncAttributeMaxDynamicSharedMemorySize, dyn_smem);
        attr_set = 1;
    }
    dim3 grid(T_DIM / BT, 8 * 16);
    attn_flash_kernel<<<grid, 128, dyn_smem>>>(qkv, bias, out);
}